// round 8
// baseline (speedup 1.0000x reference)
#include <cuda_runtime.h>
#include <cuda_bf16.h>
#include <cstdint>

#define NUM_CHR 24
#define N_EMB   512
#define DIM     512
#define BATCH   1024

#define MT 64          // samples per tile
#define NT 128         // dims per tile
#define KB 16          // k-chunk through smem
#define KSPLIT 4
#define KCH (N_EMB / KSPLIT)   // 128 k per split
#define MTILES 2               // handles cnt > 64
#define NTILES (DIM / NT)      // 4

typedef unsigned long long ull;

// ---------------- scratch (device-code references only) ----------------
__device__ float g_W[BATCH * N_EMB];
__device__ int   g_order[BATCH];
__device__ int   g_start[NUM_CHR + 1];
__device__ float g_part[KSPLIT * BATCH * DIM];

// ---------------- f32x2 helpers ----------------
__device__ __forceinline__ ull pack2(float lo, float hi) {
    ull r; asm("mov.b64 %0, {%1, %2};" : "=l"(r) : "f"(lo), "f"(hi)); return r;
}
__device__ __forceinline__ void unpack2(ull v, float& lo, float& hi) {
    asm("mov.b64 {%0, %1}, %2;" : "=f"(lo), "=f"(hi) : "l"(v));
}
__device__ __forceinline__ void ffma2(ull& d, ull a, ull b) {
    asm("fma.rn.f32x2 %0, %1, %2, %0;" : "+l"(d) : "l"(a), "l"(b));
}

// ---------------- kernel 1: weights (warp/sample) + grouping (last block) ---
__global__ void __launch_bounds__(256) weights_group_kernel(
    const int* __restrict__ chrom,
    const float* __restrict__ pos,
    const float* __restrict__ centers,
    const float* __restrict__ logv)
{
    if (blockIdx.x == BATCH / 8) {
        __shared__ int cnt[NUM_CHR];
        __shared__ int base[NUM_CHR];
        int t = threadIdx.x;
        if (t < NUM_CHR) cnt[t] = 0;
        __syncthreads();
        int cc[4], rr[4];
#pragma unroll
        for (int i = 0; i < 4; i++) {
            int b = i * 256 + t;
            cc[i] = chrom[b];
            rr[i] = atomicAdd(&cnt[cc[i]], 1);
        }
        __syncthreads();
        if (t == 0) {
            int acc = 0;
            for (int i = 0; i < NUM_CHR; i++) {
                base[i] = acc;
                g_start[i] = acc;
                acc += cnt[i];
            }
            g_start[NUM_CHR] = acc;
        }
        __syncthreads();
#pragma unroll
        for (int i = 0; i < 4; i++)
            g_order[base[cc[i]] + rr[i]] = i * 256 + t;
        return;
    }

    int warp = threadIdx.x >> 5, lane = threadIdx.x & 31;
    int b = blockIdx.x * 8 + warp;
    int c = chrom[b];
    float p = pos[b];

    const float* crow = centers + (size_t)c * N_EMB;
    const float* vrow = logv + (size_t)c * N_EMB;
    int n0 = lane * 16;

    float w[16];
    float s = 0.f;
#pragma unroll
    for (int i = 0; i < 4; i++) {
        float4 cc = *(const float4*)(crow + n0 + i * 4);
        float4 lv = *(const float4*)(vrow + n0 + i * 4);
        float d, iv;
        d = p - cc.x; iv = __expf(-lv.x); w[i*4+0] = __expf(-0.5f * d * d * iv);
        d = p - cc.y; iv = __expf(-lv.y); w[i*4+1] = __expf(-0.5f * d * d * iv);
        d = p - cc.z; iv = __expf(-lv.z); w[i*4+2] = __expf(-0.5f * d * d * iv);
        d = p - cc.w; iv = __expf(-lv.w); w[i*4+3] = __expf(-0.5f * d * d * iv);
        s += w[i*4+0] + w[i*4+1] + w[i*4+2] + w[i*4+3];
    }
#pragma unroll
    for (int off = 16; off > 0; off >>= 1)
        s += __shfl_xor_sync(0xffffffffu, s, off);
    float inv = 1.f / s;

    float* wrow = g_W + (size_t)b * N_EMB + n0;
#pragma unroll
    for (int i = 0; i < 4; i++) {
        *(float4*)(wrow + i * 4) = make_float4(w[i*4+0] * inv, w[i*4+1] * inv,
                                               w[i*4+2] * inv, w[i*4+3] * inv);
    }
}

// ---------------- kernel 2: grouped GEMM, split-K, pre-packed A ------------
// Block M64 x N128 x K128, 256 threads, micro-tile 8m x 4n.
__global__ void __launch_bounds__(256, 3) gemm_kernel(const float* __restrict__ E)
{
    int c  = blockIdx.z;
    int nt = blockIdx.x;
    int ks = blockIdx.y >> 1;
    int mt = blockIdx.y & 1;

    __shared__ __align__(16) ull   As[KB][MT];    // (w, w) packed pairs
    __shared__ __align__(16) float Bs[KB][NT];
    __shared__ int sord[MT];

    int tid = threadIdx.x;
    int d0  = nt * NT;
    int kbase = ks * KCH;

    // ---- PDL: prefetch first B chunk (blockIdx-only dependence) ----
    const float* Eb0 = E + ((size_t)c * N_EMB + kbase) * DIM + d0;
#pragma unroll
    for (int j = 0; j < 2; j++) {
        int f  = j * 256 + tid;
        int r  = f >> 5;
        int c4 = (f & 31) * 4;
        *(float4*)&Bs[r][c4] = *(const float4*)(Eb0 + (size_t)r * DIM + c4);
    }

    cudaGridDependencySynchronize();

    int s0  = g_start[c];
    int cnt = g_start[c + 1] - s0;
    int m0  = mt * MT;
    if (m0 >= cnt) return;

    if (tid < MT) {
        int g = m0 + tid;
        sord[tid] = (g < cnt) ? g_order[s0 + g] : -1;
    }
    __syncthreads();

    // A-load: thread -> (m row 0..63, 4-wide k quarter)
    int am = tid & 63;
    int ak = (tid >> 6) * 4;      // 0,4,8,12
    int samp = sord[am];
    const float* wrow = (samp >= 0) ? (g_W + (size_t)samp * N_EMB) : g_W;

    int tx = tid & 31;
    int ty = tid >> 5;

    ull acc[8][2];
#pragma unroll
    for (int i = 0; i < 8; i++) { acc[i][0] = 0ull; acc[i][1] = 0ull; }

    for (int k0 = kbase; k0 < kbase + KCH; k0 += KB) {
        // ---- A tile: one float4 per thread, pre-packed ----
        if (samp >= 0) {
            float4 v = *(const float4*)(wrow + k0 + ak);
            As[ak + 0][am] = pack2(v.x, v.x);
            As[ak + 1][am] = pack2(v.y, v.y);
            As[ak + 2][am] = pack2(v.z, v.z);
            As[ak + 3][am] = pack2(v.w, v.w);
        } else {
#pragma unroll
            for (int j = 0; j < 4; j++) As[ak + j][am] = 0ull;
        }
        // ---- B tile (first chunk already prefetched) ----
        if (k0 != kbase) {
            const float* Eb = E + ((size_t)c * N_EMB + k0) * DIM + d0;
#pragma unroll
            for (int j = 0; j < 2; j++) {
                int f  = j * 256 + tid;
                int r  = f >> 5;
                int c4 = (f & 31) * 4;
                *(float4*)&Bs[r][c4] = *(const float4*)(Eb + (size_t)r * DIM + c4);
            }
        }
        __syncthreads();

        // ---- compute: 16 ffma2 + 5 LDS per kk ----
#pragma unroll
        for (int kk = 0; kk < KB; kk++) {
            const ull* alo = &As[kk][ty * 4];        // warp-broadcast
            const ull* ahi = &As[kk][32 + ty * 4];   // warp-broadcast
            ull a0 = alo[0], a1 = alo[1], a2 = alo[2], a3 = alo[3];
            ull a4 = ahi[0], a5 = ahi[1], a6 = ahi[2], a7 = ahi[3];
            const ull* bp = (const ull*)&Bs[kk][tx * 4];
            ull b0 = bp[0], b1 = bp[1];
            ffma2(acc[0][0], a0, b0); ffma2(acc[0][1], a0, b1);
            ffma2(acc[1][0], a1, b0); ffma2(acc[1][1], a1, b1);
            ffma2(acc[2][0], a2, b0); ffma2(acc[2][1], a2, b1);
            ffma2(acc[3][0], a3, b0); ffma2(acc[3][1], a3, b1);
            ffma2(acc[4][0], a4, b0); ffma2(acc[4][1], a4, b1);
            ffma2(acc[5][0], a5, b0); ffma2(acc[5][1], a5, b1);
            ffma2(acc[6][0], a6, b0); ffma2(acc[6][1], a6, b1);
            ffma2(acc[7][0], a7, b0); ffma2(acc[7][1], a7, b1);
        }
        __syncthreads();
    }

    // ---- epilogue -> split-K partials ----
    float* pbase = g_part + (size_t)ks * BATCH * DIM;
#pragma unroll
    for (int i = 0; i < 8; i++) {
        int mi  = (i < 4) ? (ty * 4 + i) : (32 + ty * 4 + (i - 4));
        int gmi = m0 + mi;
        if (gmi < cnt) {
            int b = sord[mi];
            float x0, x1, x2, x3;
            unpack2(acc[i][0], x0, x1);
            unpack2(acc[i][1], x2, x3);
            *(float4*)(pbase + (size_t)b * DIM + d0 + tx * 4) =
                make_float4(x0, x1, x2, x3);
        }
    }
}

// ---------------- kernel 3: fixed-order split-K reduce ----------------
__global__ void __launch_bounds__(256) reduce_kernel(float* __restrict__ out)
{
    cudaGridDependencySynchronize();
    int i = (blockIdx.x * 256 + threadIdx.x) * 8;
    const size_t S = (size_t)BATCH * DIM;
    float4 a0 = __ldcs((const float4*)(g_part + i));
    float4 a1 = __ldcs((const float4*)(g_part + i + 4));
    float4 b0 = __ldcs((const float4*)(g_part + S + i));
    float4 b1 = __ldcs((const float4*)(g_part + S + i + 4));
    float4 c0 = __ldcs((const float4*)(g_part + 2 * S + i));
    float4 c1 = __ldcs((const float4*)(g_part + 2 * S + i + 4));
    float4 d0 = __ldcs((const float4*)(g_part + 3 * S + i));
    float4 d1 = __ldcs((const float4*)(g_part + 3 * S + i + 4));
    *(float4*)(out + i) = make_float4(
        (a0.x + b0.x) + (c0.x + d0.x),
        (a0.y + b0.y) + (c0.y + d0.y),
        (a0.z + b0.z) + (c0.z + d0.z),
        (a0.w + b0.w) + (c0.w + d0.w));
    *(float4*)(out + i + 4) = make_float4(
        (a1.x + b1.x) + (c1.x + d1.x),
        (a1.y + b1.y) + (c1.y + d1.y),
        (a1.z + b1.z) + (c1.z + d1.z),
        (a1.w + b1.w) + (c1.w + d1.w));
}

// ---------------- launch ----------------
extern "C" void kernel_launch(void* const* d_in, const int* in_sizes, int n_in,
                              void* d_out, int out_size)
{
    const int*   chrom    = (const int*)d_in[0];
    const float* position = (const float*)d_in[1];
    const float* embed    = (const float*)d_in[2];
    const float* centers  = (const float*)d_in[3];
    const float* logv     = (const float*)d_in[4];
    float*       out      = (float*)d_out;

    weights_group_kernel<<<BATCH / 8 + 1, 256>>>(chrom, position, centers, logv);

    cudaLaunchAttribute attr[1];
    attr[0].id = cudaLaunchAttributeProgrammaticStreamSerialization;
    attr[0].val.programmaticStreamSerializationAllowed = 1;

    dim3 grid(NTILES, KSPLIT * MTILES, NUM_CHR);   // (4, 8, 24)
    cudaLaunchConfig_t cfg{};
    cfg.gridDim = grid;
    cfg.blockDim = dim3(256, 1, 1);
    cfg.dynamicSmemBytes = 0;
    cfg.stream = 0;
    cfg.attrs = attr;
    cfg.numAttrs = 1;
    cudaLaunchKernelEx(&cfg, gemm_kernel, embed);

    cudaLaunchConfig_t cfg2{};
    cfg2.gridDim = dim3(BATCH * DIM / (256 * 8), 1, 1);
    cfg2.blockDim = dim3(256, 1, 1);
    cfg2.dynamicSmemBytes = 0;
    cfg2.stream = 0;
    cfg2.attrs = attr;
    cfg2.numAttrs = 1;
    cudaLaunchKernelEx(&cfg2, reduce_kernel, out);
}

// round 9
// speedup vs baseline: 1.0495x; 1.0495x over previous
#include <cuda_runtime.h>
#include <cuda_bf16.h>
#include <cstdint>

#define NUM_CHR 24
#define N_EMB   512
#define DIM     512
#define BATCH   1024

#define MT 64          // samples per tile
#define NT 128         // dims per tile
#define KB 16          // k-chunk through smem
#define KSPLIT 4
#define KCH (N_EMB / KSPLIT)   // 128 k per split
#define MTILES 2               // handles cnt > 64
#define NTILES (DIM / NT)      // 4

typedef unsigned long long ull;

// ---------------- scratch (device-code references only) ----------------
__device__ int   g_order[BATCH];
__device__ int   g_start[NUM_CHR + 1];
__device__ float g_part[KSPLIT * BATCH * DIM];
__device__ float g_wsum[KSPLIT * BATCH];

// ---------------- f32x2 helpers ----------------
__device__ __forceinline__ ull pack2(float lo, float hi) {
    ull r; asm("mov.b64 %0, {%1, %2};" : "=l"(r) : "f"(lo), "f"(hi)); return r;
}
__device__ __forceinline__ void unpack2(ull v, float& lo, float& hi) {
    asm("mov.b64 {%0, %1}, %2;" : "=f"(lo), "=f"(hi) : "l"(v));
}
__device__ __forceinline__ void ffma2(ull& d, ull a, ull b) {
    asm("fma.rn.f32x2 %0, %1, %2, %0;" : "+l"(d) : "l"(a), "l"(b));
}

// ---------------- kernel 1: group samples by chromosome (1 block) ----------
__global__ void __launch_bounds__(1024) group_kernel(const int* __restrict__ chrom)
{
    __shared__ int cnt[NUM_CHR];
    __shared__ int base[NUM_CHR];
    int t = threadIdx.x;
    if (t < NUM_CHR) cnt[t] = 0;
    __syncthreads();
    int c = chrom[t];
    int r = atomicAdd(&cnt[c], 1);
    __syncthreads();
    if (t == 0) {
        int acc = 0;
        for (int i = 0; i < NUM_CHR; i++) {
            base[i] = acc;
            g_start[i] = acc;
            acc += cnt[i];
        }
        g_start[NUM_CHR] = acc;
    }
    __syncthreads();
    g_order[base[c] + r] = t;
}

// ---------------- kernel 2: grouped GEMM w/ inline RBF weights, split-K ----
// Block M64 x N128 x K128, 256 threads, micro-tile 8m x 4n, pre-packed A.
// A values computed on the fly: w = exp(-(p-c)^2 * 0.5*exp(-lv)) (UNNORMALIZED);
// per-sample k-chunk sums stored to g_wsum for post-normalization in reduce.
__global__ void __launch_bounds__(256, 3) gemm_kernel(
    const float* __restrict__ E,
    const float* __restrict__ pos,
    const float* __restrict__ centers,
    const float* __restrict__ logv)
{
    int c  = blockIdx.z;
    int nt = blockIdx.x;
    int ks = blockIdx.y >> 1;
    int mt = blockIdx.y & 1;

    int s0  = g_start[c];
    int cnt = g_start[c + 1] - s0;
    int m0  = mt * MT;
    if (m0 >= cnt) return;

    __shared__ __align__(16) ull   As[KB][MT];    // (w, w) packed pairs
    __shared__ __align__(16) float Bs[KB][NT];
    __shared__ float scen[KCH];                   // centers slice
    __shared__ float shiv[KCH];                   // 0.5 * exp(-logv) slice
    __shared__ float spos[MT];
    __shared__ int   sord[MT];
    __shared__ float swsum[4][MT];

    int tid = threadIdx.x;
    int d0  = nt * NT;
    int kbase = ks * KCH;

    if (tid < MT) {
        int g = m0 + tid;
        int s = (g < cnt) ? g_order[s0 + g] : -1;
        sord[tid] = s;
        spos[tid] = (s >= 0) ? pos[s] : 0.f;
    }
    if (tid < 128) {
        shiv[tid] = 0.5f * __expf(-logv[(size_t)c * N_EMB + kbase + tid]);
    } else {
        int k = tid - 128;
        scen[k] = centers[(size_t)c * N_EMB + kbase + k];
    }
    __syncthreads();

    int am  = tid & 63;
    int akq = (tid >> 6) * 4;     // 0,4,8,12 (k quarter inside chunk)
    int samp = sord[am];
    float p  = spos[am];

    int tx = tid & 31;
    int ty = tid >> 5;

    ull acc[8][2];
#pragma unroll
    for (int i = 0; i < 8; i++) { acc[i][0] = 0ull; acc[i][1] = 0ull; }
    float ws = 0.f;

    for (int ch = 0; ch < KCH; ch += KB) {
        // ---- A tile: compute 4 unnormalized RBF weights ----
#pragma unroll
        for (int j = 0; j < 4; j++) {
            int k = ch + akq + j;
            float d = p - scen[k];
            float w = __expf(-d * d * shiv[k]);
            w = (samp >= 0) ? w : 0.f;
            ws += w;
            As[akq + j][am] = pack2(w, w);
        }
        // ---- B tile: 2 float4 per thread, coalesced ----
        const float* Eb = E + ((size_t)c * N_EMB + kbase + ch) * DIM + d0;
#pragma unroll
        for (int j = 0; j < 2; j++) {
            int f  = j * 256 + tid;
            int r  = f >> 5;
            int c4 = (f & 31) * 4;
            *(float4*)&Bs[r][c4] = *(const float4*)(Eb + (size_t)r * DIM + c4);
        }
        __syncthreads();

        // ---- compute: 16 ffma2 + 5 broadcast/conflict-free LDS per kk ----
#pragma unroll
        for (int kk = 0; kk < KB; kk++) {
            const ull* alo = &As[kk][ty * 4];
            const ull* ahi = &As[kk][32 + ty * 4];
            ull a0 = alo[0], a1 = alo[1], a2 = alo[2], a3 = alo[3];
            ull a4 = ahi[0], a5 = ahi[1], a6 = ahi[2], a7 = ahi[3];
            const ull* bp = (const ull*)&Bs[kk][tx * 4];
            ull b0 = bp[0], b1 = bp[1];
            ffma2(acc[0][0], a0, b0); ffma2(acc[0][1], a0, b1);
            ffma2(acc[1][0], a1, b0); ffma2(acc[1][1], a1, b1);
            ffma2(acc[2][0], a2, b0); ffma2(acc[2][1], a2, b1);
            ffma2(acc[3][0], a3, b0); ffma2(acc[3][1], a3, b1);
            ffma2(acc[4][0], a4, b0); ffma2(acc[4][1], a4, b1);
            ffma2(acc[5][0], a5, b0); ffma2(acc[5][1], a5, b1);
            ffma2(acc[6][0], a6, b0); ffma2(acc[6][1], a6, b1);
            ffma2(acc[7][0], a7, b0); ffma2(acc[7][1], a7, b1);
        }
        __syncthreads();
    }

    // ---- per-sample weight sums (identical across nt blocks; benign dup) ----
    swsum[tid >> 6][am] = ws;
    __syncthreads();
    if (tid < MT) {
        int s = sord[tid];
        if (s >= 0)
            g_wsum[ks * BATCH + s] =
                (swsum[0][tid] + swsum[1][tid]) + (swsum[2][tid] + swsum[3][tid]);
    }

    // ---- epilogue -> split-K partials ----
    float* pbase = g_part + (size_t)ks * BATCH * DIM;
#pragma unroll
    for (int i = 0; i < 8; i++) {
        int mi  = (i < 4) ? (ty * 4 + i) : (32 + ty * 4 + (i - 4));
        int gmi = m0 + mi;
        if (gmi < cnt) {
            int b = sord[mi];
            float x0, x1, x2, x3;
            unpack2(acc[i][0], x0, x1);
            unpack2(acc[i][1], x2, x3);
            *(float4*)(pbase + (size_t)b * DIM + d0 + tx * 4) =
                make_float4(x0, x1, x2, x3);
        }
    }
}

// ---------------- kernel 3: split-K reduce + normalization ----------------
__global__ void __launch_bounds__(256) reduce_kernel(float* __restrict__ out)
{
    int i = (blockIdx.x * 256 + threadIdx.x) * 8;
    int b = i >> 9;                                  // sample = i / DIM
    float total = (g_wsum[b] + g_wsum[BATCH + b]) +
                  (g_wsum[2 * BATCH + b] + g_wsum[3 * BATCH + b]);
    float inv = 1.f / total;

    const size_t S = (size_t)BATCH * DIM;
    float4 a0 = *(const float4*)(g_part + i);
    float4 a1 = *(const float4*)(g_part + i + 4);
    float4 b0 = *(const float4*)(g_part + S + i);
    float4 b1 = *(const float4*)(g_part + S + i + 4);
    float4 c0 = *(const float4*)(g_part + 2 * S + i);
    float4 c1 = *(const float4*)(g_part + 2 * S + i + 4);
    float4 d0 = *(const float4*)(g_part + 3 * S + i);
    float4 d1 = *(const float4*)(g_part + 3 * S + i + 4);
    *(float4*)(out + i) = make_float4(
        ((a0.x + b0.x) + (c0.x + d0.x)) * inv,
        ((a0.y + b0.y) + (c0.y + d0.y)) * inv,
        ((a0.z + b0.z) + (c0.z + d0.z)) * inv,
        ((a0.w + b0.w) + (c0.w + d0.w)) * inv);
    *(float4*)(out + i + 4) = make_float4(
        ((a1.x + b1.x) + (c1.x + d1.x)) * inv,
        ((a1.y + b1.y) + (c1.y + d1.y)) * inv,
        ((a1.z + b1.z) + (c1.z + d1.z)) * inv,
        ((a1.w + b1.w) + (c1.w + d1.w)) * inv);
}

// ---------------- launch ----------------
extern "C" void kernel_launch(void* const* d_in, const int* in_sizes, int n_in,
                              void* d_out, int out_size)
{
    const int*   chrom    = (const int*)d_in[0];
    const float* position = (const float*)d_in[1];
    const float* embed    = (const float*)d_in[2];
    const float* centers  = (const float*)d_in[3];
    const float* logv     = (const float*)d_in[4];
    float*       out      = (float*)d_out;

    group_kernel<<<1, 1024>>>(chrom);

    dim3 grid(NTILES, KSPLIT * MTILES, NUM_CHR);   // (4, 8, 24)
    gemm_kernel<<<grid, 256>>>(embed, position, centers, logv);

    reduce_kernel<<<BATCH * DIM / (256 * 8), 256>>>(out);
}

// round 10
// speedup vs baseline: 1.0571x; 1.0072x over previous
#include <cuda_runtime.h>
#include <cuda_bf16.h>
#include <cstdint>

#define NUM_CHR 24
#define N_EMB   512
#define DIM     512
#define BATCH   1024

#define MT 64          // samples per tile
#define NT 128         // dims per tile
#define KB 32          // k-chunk through smem
#define KSPLIT 4
#define KCH (N_EMB / KSPLIT)   // 128 k per split
#define MTILES 2               // handles cnt > 64
#define NTILES (DIM / NT)      // 4

typedef unsigned long long ull;

// ---------------- scratch (device-code references only) ----------------
__device__ float g_part[KSPLIT * BATCH * DIM];
__device__ float g_wsum[KSPLIT * BATCH];

// ---------------- f32x2 helpers ----------------
__device__ __forceinline__ ull pack2(float lo, float hi) {
    ull r; asm("mov.b64 %0, {%1, %2};" : "=l"(r) : "f"(lo), "f"(hi)); return r;
}
__device__ __forceinline__ void unpack2(ull v, float& lo, float& hi) {
    asm("mov.b64 {%0, %1}, %2;" : "=f"(lo), "=f"(hi) : "l"(v));
}
__device__ __forceinline__ void ffma2(ull& d, ull a, ull b) {
    asm("fma.rn.f32x2 %0, %1, %2, %0;" : "+l"(d) : "l"(a), "l"(b));
}

// ---------------- kernel 1: grouped GEMM, in-block deterministic grouping --
// Block M64 x N128 x K128, 256 threads, micro-tile 8m x 4n, pre-packed A.
// Weights computed inline (unnormalized); normalization deferred to reduce.
__global__ void __launch_bounds__(256, 3) gemm_kernel(
    const float* __restrict__ E,
    const int*   __restrict__ chrom,
    const float* __restrict__ pos,
    const float* __restrict__ centers,
    const float* __restrict__ logv)
{
    int c  = blockIdx.z;
    int nt = blockIdx.x;
    int ks = blockIdx.y >> 1;
    int mt = blockIdx.y & 1;
    int m0 = mt * MT;

    __shared__ __align__(16) ull   As[KB][MT];
    __shared__ __align__(16) float Bs[KB][NT];
    __shared__ float scen[KCH];
    __shared__ float shiv[KCH];
    __shared__ float spos[MT];
    __shared__ int   sord[MT];
    __shared__ float swsum[4][MT];
    __shared__ int   wtot[8];
    __shared__ int   s_cnt;

    int tid  = threadIdx.x;
    int lane = tid & 31, w5 = tid >> 5;
    int d0   = nt * NT;
    int kbase = ks * KCH;

    // ---- deterministic in-block grouping: blocked predicate prefix-scan ----
    if (tid < MT) sord[tid] = -1;
    int i0 = tid * 4;
    int c0v = chrom[i0], c1v = chrom[i0 + 1], c2v = chrom[i0 + 2], c3v = chrom[i0 + 3];
    int p0 = (c0v == c), p1 = (c1v == c), p2 = (c2v == c), p3 = (c3v == c);
    int local = p0 + p1 + p2 + p3;
    int scan = local;
#pragma unroll
    for (int off = 1; off < 32; off <<= 1) {
        int n = __shfl_up_sync(0xffffffffu, scan, off);
        if (lane >= off) scan += n;
    }
    if (lane == 31) wtot[w5] = scan;
    __syncthreads();
    if (tid == 0) {
        int acc = 0;
#pragma unroll
        for (int i = 0; i < 8; i++) { int t = wtot[i]; wtot[i] = acc; acc += t; }
        s_cnt = acc;
    }
    __syncthreads();
    int base = wtot[w5] + scan - local;
    {
        int pp = base;
        if (p0) { if (pp >= m0 && pp < m0 + MT) sord[pp - m0] = i0;     pp++; }
        if (p1) { if (pp >= m0 && pp < m0 + MT) sord[pp - m0] = i0 + 1; pp++; }
        if (p2) { if (pp >= m0 && pp < m0 + MT) sord[pp - m0] = i0 + 2; pp++; }
        if (p3) { if (pp >= m0 && pp < m0 + MT) sord[pp - m0] = i0 + 3; pp++; }
    }
    __syncthreads();
    int cnt = s_cnt;
    if (m0 >= cnt) return;

    // ---- parameter slices + positions ----
    if (tid < MT) {
        int s = sord[tid];
        spos[tid] = (s >= 0) ? pos[s] : 0.f;
    }
    if (tid < 128) {
        shiv[tid] = 0.5f * __expf(-logv[(size_t)c * N_EMB + kbase + tid]);
    } else {
        int k = tid - 128;
        scen[k] = centers[(size_t)c * N_EMB + kbase + k];
    }
    __syncthreads();

    int am  = tid & 63;
    int akq = (tid >> 6) * 8;     // 8-wide k segment inside 32-chunk
    int samp = sord[am];
    float p  = spos[am];

    int tx = tid & 31;
    int ty = tid >> 5;

    ull acc[8][2];
#pragma unroll
    for (int i = 0; i < 8; i++) { acc[i][0] = 0ull; acc[i][1] = 0ull; }
    float ws = 0.f;

    for (int ch = 0; ch < KCH; ch += KB) {
        // ---- A tile: 8 unnormalized RBF weights per thread ----
#pragma unroll
        for (int j = 0; j < 8; j++) {
            int k = ch + akq + j;
            float d = p - scen[k];
            float w = __expf(-d * d * shiv[k]);
            w = (samp >= 0) ? w : 0.f;
            ws += w;
            As[akq + j][am] = pack2(w, w);
        }
        // ---- B tile: 4 float4 per thread, coalesced ----
        const float* Eb = E + ((size_t)c * N_EMB + kbase + ch) * DIM + d0;
#pragma unroll
        for (int j = 0; j < 4; j++) {
            int f  = j * 256 + tid;
            int r  = f >> 5;
            int c4 = (f & 31) * 4;
            *(float4*)&Bs[r][c4] = *(const float4*)(Eb + (size_t)r * DIM + c4);
        }
        __syncthreads();

        // ---- compute: 16 ffma2 + 5 broadcast/conflict-free LDS per kk ----
#pragma unroll
        for (int kk = 0; kk < KB; kk++) {
            const ull* alo = &As[kk][ty * 4];
            const ull* ahi = &As[kk][32 + ty * 4];
            ull a0 = alo[0], a1 = alo[1], a2 = alo[2], a3 = alo[3];
            ull a4 = ahi[0], a5 = ahi[1], a6 = ahi[2], a7 = ahi[3];
            const ull* bp = (const ull*)&Bs[kk][tx * 4];
            ull b0 = bp[0], b1 = bp[1];
            ffma2(acc[0][0], a0, b0); ffma2(acc[0][1], a0, b1);
            ffma2(acc[1][0], a1, b0); ffma2(acc[1][1], a1, b1);
            ffma2(acc[2][0], a2, b0); ffma2(acc[2][1], a2, b1);
            ffma2(acc[3][0], a3, b0); ffma2(acc[3][1], a3, b1);
            ffma2(acc[4][0], a4, b0); ffma2(acc[4][1], a4, b1);
            ffma2(acc[5][0], a5, b0); ffma2(acc[5][1], a5, b1);
            ffma2(acc[6][0], a6, b0); ffma2(acc[6][1], a6, b1);
            ffma2(acc[7][0], a7, b0); ffma2(acc[7][1], a7, b1);
        }
        __syncthreads();
    }

    // ---- per-sample weight sums (identical across nt blocks; benign dup) ----
    swsum[tid >> 6][am] = ws;
    __syncthreads();
    if (tid < MT) {
        int s = sord[tid];
        if (s >= 0)
            g_wsum[ks * BATCH + s] =
                (swsum[0][tid] + swsum[1][tid]) + (swsum[2][tid] + swsum[3][tid]);
    }

    // ---- epilogue -> split-K partials ----
    float* pbase = g_part + (size_t)ks * BATCH * DIM;
#pragma unroll
    for (int i = 0; i < 8; i++) {
        int mi  = (i < 4) ? (ty * 4 + i) : (32 + ty * 4 + (i - 4));
        int gmi = m0 + mi;
        if (gmi < cnt) {
            int b = sord[mi];
            float x0, x1, x2, x3;
            unpack2(acc[i][0], x0, x1);
            unpack2(acc[i][1], x2, x3);
            *(float4*)(pbase + (size_t)b * DIM + d0 + tx * 4) =
                make_float4(x0, x1, x2, x3);
        }
    }
}

// ---------------- kernel 2: split-K reduce + normalization ----------------
__global__ void __launch_bounds__(256) reduce_kernel(float* __restrict__ out)
{
    int i = (blockIdx.x * 256 + threadIdx.x) * 8;
    int b = i >> 9;
    float total = (g_wsum[b] + g_wsum[BATCH + b]) +
                  (g_wsum[2 * BATCH + b] + g_wsum[3 * BATCH + b]);
    float inv = 1.f / total;

    const size_t S = (size_t)BATCH * DIM;
    float4 a0 = *(const float4*)(g_part + i);
    float4 a1 = *(const float4*)(g_part + i + 4);
    float4 b0 = *(const float4*)(g_part + S + i);
    float4 b1 = *(const float4*)(g_part + S + i + 4);
    float4 c0 = *(const float4*)(g_part + 2 * S + i);
    float4 c1 = *(const float4*)(g_part + 2 * S + i + 4);
    float4 d0 = *(const float4*)(g_part + 3 * S + i);
    float4 d1 = *(const float4*)(g_part + 3 * S + i + 4);
    *(float4*)(out + i) = make_float4(
        ((a0.x + b0.x) + (c0.x + d0.x)) * inv,
        ((a0.y + b0.y) + (c0.y + d0.y)) * inv,
        ((a0.z + b0.z) + (c0.z + d0.z)) * inv,
        ((a0.w + b0.w) + (c0.w + d0.w)) * inv);
    *(float4*)(out + i + 4) = make_float4(
        ((a1.x + b1.x) + (c1.x + d1.x)) * inv,
        ((a1.y + b1.y) + (c1.y + d1.y)) * inv,
        ((a1.z + b1.z) + (c1.z + d1.z)) * inv,
        ((a1.w + b1.w) + (c1.w + d1.w)) * inv);
}

// ---------------- launch ----------------
extern "C" void kernel_launch(void* const* d_in, const int* in_sizes, int n_in,
                              void* d_out, int out_size)
{
    const int*   chrom    = (const int*)d_in[0];
    const float* position = (const float*)d_in[1];
    const float* embed    = (const float*)d_in[2];
    const float* centers  = (const float*)d_in[3];
    const float* logv     = (const float*)d_in[4];
    float*       out      = (float*)d_out;

    dim3 grid(NTILES, KSPLIT * MTILES, NUM_CHR);   // (4, 8, 24)
    gemm_kernel<<<grid, 256>>>(embed, chrom, position, centers, logv);

    reduce_kernel<<<BATCH * DIM / (256 * 8), 256>>>(out);
}

// round 11
// speedup vs baseline: 1.6030x; 1.5165x over previous
#include <cuda_runtime.h>
#include <cuda_bf16.h>
#include <cstdint>

#define NUM_CHR 24
#define N_EMB   512
#define DIM     512
#define BATCH   1024

#define MT 64
#define NT 128
#define KB 32
#define KSPLIT 4
#define KCH (N_EMB / KSPLIT)   // 128
#define MTILES 2
#define NTILES (DIM / NT)      // 4

#define AS_STRIDE 72            // words; bank(k,m) = (8k + m) % 32
#define BS_STRIDE 136           // words; bank(k,n) = (8k + n) % 32

// ---------------- scratch (device-code references only) ----------------
__device__ float g_W[BATCH * N_EMB];
__device__ int   g_order[BATCH];
__device__ int   g_start[NUM_CHR + 1];
__device__ float g_part[KSPLIT * BATCH * DIM];

// ---------------- tf32 helpers ----------------
__device__ __forceinline__ uint32_t f2tf(float f) {
    uint32_t r; asm("cvt.rna.tf32.f32 %0, %1;" : "=r"(r) : "f"(f)); return r;
}
#define HMMA(d, a0, a1, a2, a3, b0, b1)                                      \
    asm("mma.sync.aligned.m16n8k8.row.col.f32.tf32.tf32.f32 "                \
        "{%0,%1,%2,%3},{%4,%5,%6,%7},{%8,%9},{%0,%1,%2,%3};"                 \
        : "+f"((d)[0]), "+f"((d)[1]), "+f"((d)[2]), "+f"((d)[3])             \
        : "r"(a0), "r"(a1), "r"(a2), "r"(a3), "r"(b0), "r"(b1))

// ---------------- kernel 1: weights (warp/sample) + grouping (last block) ---
__global__ void __launch_bounds__(256) weights_group_kernel(
    const int* __restrict__ chrom,
    const float* __restrict__ pos,
    const float* __restrict__ centers,
    const float* __restrict__ logv)
{
    if (blockIdx.x == BATCH / 8) {
        __shared__ int cnt[NUM_CHR];
        __shared__ int base[NUM_CHR];
        int t = threadIdx.x;
        if (t < NUM_CHR) cnt[t] = 0;
        __syncthreads();
        int cc[4], rr[4];
#pragma unroll
        for (int i = 0; i < 4; i++) {
            int b = i * 256 + t;
            cc[i] = chrom[b];
            rr[i] = atomicAdd(&cnt[cc[i]], 1);
        }
        __syncthreads();
        if (t == 0) {
            int acc = 0;
            for (int i = 0; i < NUM_CHR; i++) {
                base[i] = acc;
                g_start[i] = acc;
                acc += cnt[i];
            }
            g_start[NUM_CHR] = acc;
        }
        __syncthreads();
#pragma unroll
        for (int i = 0; i < 4; i++)
            g_order[base[cc[i]] + rr[i]] = i * 256 + t;
        return;
    }

    int warp = threadIdx.x >> 5, lane = threadIdx.x & 31;
    int b = blockIdx.x * 8 + warp;
    int c = chrom[b];
    float p = pos[b];

    const float* crow = centers + (size_t)c * N_EMB;
    const float* vrow = logv + (size_t)c * N_EMB;
    int n0 = lane * 16;

    float w[16];
    float s = 0.f;
#pragma unroll
    for (int i = 0; i < 4; i++) {
        float4 cc = *(const float4*)(crow + n0 + i * 4);
        float4 lv = *(const float4*)(vrow + n0 + i * 4);
        float d, iv;
        d = p - cc.x; iv = __expf(-lv.x); w[i*4+0] = __expf(-0.5f * d * d * iv);
        d = p - cc.y; iv = __expf(-lv.y); w[i*4+1] = __expf(-0.5f * d * d * iv);
        d = p - cc.z; iv = __expf(-lv.z); w[i*4+2] = __expf(-0.5f * d * d * iv);
        d = p - cc.w; iv = __expf(-lv.w); w[i*4+3] = __expf(-0.5f * d * d * iv);
        s += w[i*4+0] + w[i*4+1] + w[i*4+2] + w[i*4+3];
    }
#pragma unroll
    for (int off = 16; off > 0; off >>= 1)
        s += __shfl_xor_sync(0xffffffffu, s, off);
    float inv = 1.f / s;

    float* wrow = g_W + (size_t)b * N_EMB + n0;
#pragma unroll
    for (int i = 0; i < 4; i++) {
        *(float4*)(wrow + i * 4) = make_float4(w[i*4+0] * inv, w[i*4+1] * inv,
                                               w[i*4+2] * inv, w[i*4+3] * inv);
    }
}

// ---------------- kernel 2: grouped GEMM, tf32 mma.sync, split-K ----------
// Block M64 x N128 x K128, 256 threads = 8 warps in 4m x 2n grid.
// Each warp: m16 x n64 slab, 8 HMMA per k8-step.
__global__ void __launch_bounds__(256, 3) gemm_kernel(const float* __restrict__ E)
{
    int c  = blockIdx.z;
    int nt = blockIdx.x;
    int ks = blockIdx.y >> 1;
    int mt = blockIdx.y & 1;

    int s0  = g_start[c];
    int cnt = g_start[c + 1] - s0;
    int m0  = mt * MT;
    if (m0 >= cnt) return;

    __shared__ __align__(16) float As[KB][AS_STRIDE];   // tf32 bits, [k][m]
    __shared__ __align__(16) float Bs[KB][BS_STRIDE];   // tf32 bits, [k][n]
    __shared__ int sord[MT];

    int tid = threadIdx.x;
    int d0  = nt * NT;
    int kbase = ks * KCH;

    if (tid < MT) {
        int gmi = m0 + tid;
        sord[tid] = (gmi < cnt) ? g_order[s0 + gmi] : -1;
    }
    __syncthreads();

    // A-stage assignment: thread -> (m row, 8-wide k segment)
    int am  = tid & 63;
    int ak8 = (tid >> 6) * 8;
    int samp = sord[am];
    const float* wrow = (samp >= 0) ? (g_W + (size_t)samp * N_EMB) : g_W;

    int lane = tid & 31, warp = tid >> 5;
    int g = lane >> 2, t = lane & 3;
    int mw = (warp & 3) * 16;        // m offset of this warp's m16 slab
    int nw = (warp >> 2) * 64;       // n offset of this warp's n64 slab

    float acc[8][4];
#pragma unroll
    for (int j = 0; j < 8; j++)
#pragma unroll
        for (int i = 0; i < 4; i++) acc[j][i] = 0.f;

    for (int ch = 0; ch < KCH; ch += KB) {
        // ---- A tile: 8 weights -> tf32 -> As[k][m] ----
        if (samp >= 0) {
            float4 v0 = *(const float4*)(wrow + kbase + ch + ak8 + 0);
            float4 v1 = *(const float4*)(wrow + kbase + ch + ak8 + 4);
            As[ak8 + 0][am] = __uint_as_float(f2tf(v0.x));
            As[ak8 + 1][am] = __uint_as_float(f2tf(v0.y));
            As[ak8 + 2][am] = __uint_as_float(f2tf(v0.z));
            As[ak8 + 3][am] = __uint_as_float(f2tf(v0.w));
            As[ak8 + 4][am] = __uint_as_float(f2tf(v1.x));
            As[ak8 + 5][am] = __uint_as_float(f2tf(v1.y));
            As[ak8 + 6][am] = __uint_as_float(f2tf(v1.z));
            As[ak8 + 7][am] = __uint_as_float(f2tf(v1.w));
        } else {
#pragma unroll
            for (int j = 0; j < 8; j++) As[ak8 + j][am] = 0.f;
        }
        // ---- B tile: 4 float4 per thread -> tf32 -> Bs[k][n] ----
        const float* Eb = E + ((size_t)c * N_EMB + kbase + ch) * DIM + d0;
#pragma unroll
        for (int j = 0; j < 4; j++) {
            int f  = j * 256 + tid;
            int r  = f >> 5;            // k row 0..31
            int c4 = (f & 31) * 4;      // n col 0..124
            float4 v = *(const float4*)(Eb + (size_t)r * DIM + c4);
            float4 o;
            o.x = __uint_as_float(f2tf(v.x));
            o.y = __uint_as_float(f2tf(v.y));
            o.z = __uint_as_float(f2tf(v.z));
            o.w = __uint_as_float(f2tf(v.w));
            *(float4*)&Bs[r][c4] = o;
        }
        __syncthreads();

        // ---- compute: 4 k8-steps ----
#pragma unroll
        for (int kk = 0; kk < 4; kk++) {
            int k0 = kk * 8;
            uint32_t a0 = __float_as_uint(As[k0 + t][mw + g]);
            uint32_t a1 = __float_as_uint(As[k0 + t][mw + g + 8]);
            uint32_t a2 = __float_as_uint(As[k0 + t + 4][mw + g]);
            uint32_t a3 = __float_as_uint(As[k0 + t + 4][mw + g + 8]);
#pragma unroll
            for (int j = 0; j < 8; j++) {
                int n = nw + j * 8 + g;
                uint32_t b0 = __float_as_uint(Bs[k0 + t][n]);
                uint32_t b1 = __float_as_uint(Bs[k0 + t + 4][n]);
                HMMA(acc[j], a0, a1, a2, a3, b0, b1);
            }
        }
        __syncthreads();
    }

    // ---- epilogue -> split-K partials ----
    float* pbase = g_part + (size_t)ks * BATCH * DIM;
    int mi1 = mw + g, mi2 = mw + g + 8;
    int b1 = (m0 + mi1 < cnt) ? sord[mi1] : -1;
    int b2 = (m0 + mi2 < cnt) ? sord[mi2] : -1;
#pragma unroll
    for (int j = 0; j < 8; j++) {
        int dcol = d0 + nw + j * 8 + 2 * t;
        if (b1 >= 0)
            *(float2*)(pbase + (size_t)b1 * DIM + dcol) =
                make_float2(acc[j][0], acc[j][1]);
        if (b2 >= 0)
            *(float2*)(pbase + (size_t)b2 * DIM + dcol) =
                make_float2(acc[j][2], acc[j][3]);
    }
}

// ---------------- kernel 3: fixed-order split-K reduce ----------------
__global__ void __launch_bounds__(256) reduce_kernel(float* __restrict__ out)
{
    int i = (blockIdx.x * 256 + threadIdx.x) * 4;
    const size_t S = (size_t)BATCH * DIM;
    float4 a = *(const float4*)(g_part + i);
    float4 b = *(const float4*)(g_part + S + i);
    float4 c = *(const float4*)(g_part + 2 * S + i);
    float4 d = *(const float4*)(g_part + 3 * S + i);
    *(float4*)(out + i) = make_float4(
        (a.x + b.x) + (c.x + d.x),
        (a.y + b.y) + (c.y + d.y),
        (a.z + b.z) + (c.z + d.z),
        (a.w + b.w) + (c.w + d.w));
}

// ---------------- launch ----------------
extern "C" void kernel_launch(void* const* d_in, const int* in_sizes, int n_in,
                              void* d_out, int out_size)
{
    const int*   chrom    = (const int*)d_in[0];
    const float* position = (const float*)d_in[1];
    const float* embed    = (const float*)d_in[2];
    const float* centers  = (const float*)d_in[3];
    const float* logv     = (const float*)d_in[4];
    float*       out      = (float*)d_out;

    weights_group_kernel<<<BATCH / 8 + 1, 256>>>(chrom, position, centers, logv);

    dim3 grid(NTILES, KSPLIT * MTILES, NUM_CHR);   // (4, 8, 24)
    gemm_kernel<<<grid, 256>>>(embed);

    reduce_kernel<<<BATCH * DIM / (256 * 4), 256>>>(out);
}

// round 12
// speedup vs baseline: 1.6208x; 1.0111x over previous
#include <cuda_runtime.h>
#include <cuda_bf16.h>
#include <cstdint>

#define NUM_CHR 24
#define N_EMB   512
#define DIM     512
#define BATCH   1024

#define MT 64
#define NT 128
#define KB 32
#define KSPLIT 4
#define KCH (N_EMB / KSPLIT)   // 128
#define MTILES 2
#define NTILES (DIM / NT)      // 4

#define AS_STRIDE 72            // words; bank(k,m) = (8k + m) % 32
#define BS_STRIDE 136           // words; bank(k,n) = (8k + n) % 32

// ---------------- scratch (device-code references only) ----------------
__device__ float g_W[BATCH * N_EMB];
__device__ int   g_order[BATCH];
__device__ int   g_start[NUM_CHR + 1];
__device__ float g_part[KSPLIT * BATCH * DIM];

// ---------------- tf32 helpers ----------------
__device__ __forceinline__ uint32_t f2tf(float f) {
    uint32_t r; asm("cvt.rna.tf32.f32 %0, %1;" : "=r"(r) : "f"(f)); return r;
}
#define HMMA(d, a0, a1, a2, a3, b0, b1)                                      \
    asm("mma.sync.aligned.m16n8k8.row.col.f32.tf32.tf32.f32 "                \
        "{%0,%1,%2,%3},{%4,%5,%6,%7},{%8,%9},{%0,%1,%2,%3};"                 \
        : "+f"((d)[0]), "+f"((d)[1]), "+f"((d)[2]), "+f"((d)[3])             \
        : "r"(a0), "r"(a1), "r"(a2), "r"(a3), "r"(b0), "r"(b1))

// ---------------- kernel 1: weights (warp/sample) + atomic-free grouping ---
__global__ void __launch_bounds__(256) weights_group_kernel(
    const int* __restrict__ chrom,
    const float* __restrict__ pos,
    const float* __restrict__ centers,
    const float* __restrict__ logv)
{
    if (blockIdx.x == BATCH / 8) {
        // ---- grouping block: match_any + scans, zero atomics ----
        __shared__ int cnt[4][8][NUM_CHR];
        __shared__ int pre[4][8][NUM_CHR];
        __shared__ int base[NUM_CHR];
        __shared__ int tot[NUM_CHR];

        int t = threadIdx.x;
        int lane = t & 31, w = t >> 5;

        for (int i = t; i < 4 * 8 * NUM_CHR; i += 256) ((int*)cnt)[i] = 0;
        __syncthreads();

        int cs[4], lr[4];
#pragma unroll
        for (int r = 0; r < 4; r++) {
            int s = r * 256 + t;
            int c = chrom[s];
            unsigned mask = __match_any_sync(0xffffffffu, c);
            int leader = __ffs(mask) - 1;
            lr[r] = __popc(mask & ((1u << lane) - 1u));
            cs[r] = c;
            if (lane == leader) cnt[r][w][c] = __popc(mask);
        }
        __syncthreads();

        // per-chromosome scan over 32 (r,w) slots; warp handles chr w, w+8, w+16
        for (int c = w; c < NUM_CHR; c += 8) {
            int v = cnt[lane >> 3][lane & 7][c];
            int scan = v;
#pragma unroll
            for (int off = 1; off < 32; off <<= 1) {
                int n = __shfl_up_sync(0xffffffffu, scan, off);
                if (lane >= off) scan += n;
            }
            pre[lane >> 3][lane & 7][c] = scan - v;
            if (lane == 31) tot[c] = scan;
        }
        __syncthreads();

        if (w == 0) {
            int v = (lane < NUM_CHR) ? tot[lane] : 0;
            int scan = v;
#pragma unroll
            for (int off = 1; off < 32; off <<= 1) {
                int n = __shfl_up_sync(0xffffffffu, scan, off);
                if (lane >= off) scan += n;
            }
            if (lane < NUM_CHR) { base[lane] = scan - v; g_start[lane] = scan - v; }
            if (lane == NUM_CHR - 1) g_start[NUM_CHR] = scan;
        }
        __syncthreads();

#pragma unroll
        for (int r = 0; r < 4; r++) {
            int c = cs[r];
            g_order[base[c] + pre[r][w][c] + lr[r]] = r * 256 + t;
        }
        return;
    }

    int warp = threadIdx.x >> 5, lane = threadIdx.x & 31;
    int b = blockIdx.x * 8 + warp;
    int c = chrom[b];
    float p = pos[b];

    const float* crow = centers + (size_t)c * N_EMB;
    const float* vrow = logv + (size_t)c * N_EMB;
    int n0 = lane * 16;

    float w[16];
    float s = 0.f;
#pragma unroll
    for (int i = 0; i < 4; i++) {
        float4 cc = *(const float4*)(crow + n0 + i * 4);
        float4 lv = *(const float4*)(vrow + n0 + i * 4);
        float d, iv;
        d = p - cc.x; iv = __expf(-lv.x); w[i*4+0] = __expf(-0.5f * d * d * iv);
        d = p - cc.y; iv = __expf(-lv.y); w[i*4+1] = __expf(-0.5f * d * d * iv);
        d = p - cc.z; iv = __expf(-lv.z); w[i*4+2] = __expf(-0.5f * d * d * iv);
        d = p - cc.w; iv = __expf(-lv.w); w[i*4+3] = __expf(-0.5f * d * d * iv);
        s += w[i*4+0] + w[i*4+1] + w[i*4+2] + w[i*4+3];
    }
#pragma unroll
    for (int off = 16; off > 0; off >>= 1)
        s += __shfl_xor_sync(0xffffffffu, s, off);
    float inv = 1.f / s;

    float* wrow = g_W + (size_t)b * N_EMB + n0;
#pragma unroll
    for (int i = 0; i < 4; i++) {
        *(float4*)(wrow + i * 4) = make_float4(w[i*4+0] * inv, w[i*4+1] * inv,
                                               w[i*4+2] * inv, w[i*4+3] * inv);
    }
}

// ---------------- kernel 2: grouped GEMM, tf32 mma.sync, split-K ----------
// Block M64 x N128 x K128, 256 threads = 8 warps in 4m x 2n grid.
__global__ void __launch_bounds__(256, 3) gemm_kernel(const float* __restrict__ E)
{
    int c  = blockIdx.z;
    int nt = blockIdx.x;
    int ks = blockIdx.y >> 1;
    int mt = blockIdx.y & 1;

    int s0  = g_start[c];
    int cnt = g_start[c + 1] - s0;
    int m0  = mt * MT;
    if (m0 >= cnt) return;

    __shared__ __align__(16) float As[KB][AS_STRIDE];   // tf32 bits, [k][m]
    __shared__ __align__(16) float Bs[KB][BS_STRIDE];   // tf32 bits, [k][n]
    __shared__ int sord[MT];

    int tid = threadIdx.x;
    int d0  = nt * NT;
    int kbase = ks * KCH;

    if (tid < MT) {
        int gmi = m0 + tid;
        sord[tid] = (gmi < cnt) ? g_order[s0 + gmi] : -1;
    }
    __syncthreads();

    int am  = tid & 63;
    int ak8 = (tid >> 6) * 8;
    int samp = sord[am];
    const float* wrow = (samp >= 0) ? (g_W + (size_t)samp * N_EMB) : g_W;

    int lane = tid & 31, warp = tid >> 5;
    int g = lane >> 2, t = lane & 3;
    int mw = (warp & 3) * 16;
    int nw = (warp >> 2) * 64;

    float acc[8][4];
#pragma unroll
    for (int j = 0; j < 8; j++)
#pragma unroll
        for (int i = 0; i < 4; i++) acc[j][i] = 0.f;

    for (int ch = 0; ch < KCH; ch += KB) {
        // ---- A tile ----
        if (samp >= 0) {
            float4 v0 = *(const float4*)(wrow + kbase + ch + ak8 + 0);
            float4 v1 = *(const float4*)(wrow + kbase + ch + ak8 + 4);
            As[ak8 + 0][am] = __uint_as_float(f2tf(v0.x));
            As[ak8 + 1][am] = __uint_as_float(f2tf(v0.y));
            As[ak8 + 2][am] = __uint_as_float(f2tf(v0.z));
            As[ak8 + 3][am] = __uint_as_float(f2tf(v0.w));
            As[ak8 + 4][am] = __uint_as_float(f2tf(v1.x));
            As[ak8 + 5][am] = __uint_as_float(f2tf(v1.y));
            As[ak8 + 6][am] = __uint_as_float(f2tf(v1.z));
            As[ak8 + 7][am] = __uint_as_float(f2tf(v1.w));
        } else {
#pragma unroll
            for (int j = 0; j < 8; j++) As[ak8 + j][am] = 0.f;
        }
        // ---- B tile ----
        const float* Eb = E + ((size_t)c * N_EMB + kbase + ch) * DIM + d0;
#pragma unroll
        for (int j = 0; j < 4; j++) {
            int f  = j * 256 + tid;
            int r  = f >> 5;
            int c4 = (f & 31) * 4;
            float4 v = *(const float4*)(Eb + (size_t)r * DIM + c4);
            float4 o;
            o.x = __uint_as_float(f2tf(v.x));
            o.y = __uint_as_float(f2tf(v.y));
            o.z = __uint_as_float(f2tf(v.z));
            o.w = __uint_as_float(f2tf(v.w));
            *(float4*)&Bs[r][c4] = o;
        }
        __syncthreads();

#pragma unroll
        for (int kk = 0; kk < 4; kk++) {
            int k0 = kk * 8;
            uint32_t a0 = __float_as_uint(As[k0 + t][mw + g]);
            uint32_t a1 = __float_as_uint(As[k0 + t][mw + g + 8]);
            uint32_t a2 = __float_as_uint(As[k0 + t + 4][mw + g]);
            uint32_t a3 = __float_as_uint(As[k0 + t + 4][mw + g + 8]);
#pragma unroll
            for (int j = 0; j < 8; j++) {
                int n = nw + j * 8 + g;
                uint32_t b0 = __float_as_uint(Bs[k0 + t][n]);
                uint32_t b1 = __float_as_uint(Bs[k0 + t + 4][n]);
                HMMA(acc[j], a0, a1, a2, a3, b0, b1);
            }
        }
        __syncthreads();
    }

    // ---- epilogue -> split-K partials ----
    float* pbase = g_part + (size_t)ks * BATCH * DIM;
    int mi1 = mw + g, mi2 = mw + g + 8;
    int b1 = (m0 + mi1 < cnt) ? sord[mi1] : -1;
    int b2 = (m0 + mi2 < cnt) ? sord[mi2] : -1;
#pragma unroll
    for (int j = 0; j < 8; j++) {
        int dcol = d0 + nw + j * 8 + 2 * t;
        if (b1 >= 0)
            *(float2*)(pbase + (size_t)b1 * DIM + dcol) =
                make_float2(acc[j][0], acc[j][1]);
        if (b2 >= 0)
            *(float2*)(pbase + (size_t)b2 * DIM + dcol) =
                make_float2(acc[j][2], acc[j][3]);
    }
}

// ---------------- kernel 3: fixed-order split-K reduce ----------------
__global__ void __launch_bounds__(256) reduce_kernel(float* __restrict__ out)
{
    int i = (blockIdx.x * 256 + threadIdx.x) * 4;
    const size_t S = (size_t)BATCH * DIM;
    float4 a = *(const float4*)(g_part + i);
    float4 b = *(const float4*)(g_part + S + i);
    float4 c = *(const float4*)(g_part + 2 * S + i);
    float4 d = *(const float4*)(g_part + 3 * S + i);
    *(float4*)(out + i) = make_float4(
        (a.x + b.x) + (c.x + d.x),
        (a.y + b.y) + (c.y + d.y),
        (a.z + b.z) + (c.z + d.z),
        (a.w + b.w) + (c.w + d.w));
}

// ---------------- launch ----------------
extern "C" void kernel_launch(void* const* d_in, const int* in_sizes, int n_in,
                              void* d_out, int out_size)
{
    const int*   chrom    = (const int*)d_in[0];
    const float* position = (const float*)d_in[1];
    const float* embed    = (const float*)d_in[2];
    const float* centers  = (const float*)d_in[3];
    const float* logv     = (const float*)d_in[4];
    float*       out      = (float*)d_out;

    weights_group_kernel<<<BATCH / 8 + 1, 256>>>(chrom, position, centers, logv);

    dim3 grid(NTILES, KSPLIT * MTILES, NUM_CHR);   // (4, 8, 24)
    gemm_kernel<<<grid, 256>>>(embed);

    reduce_kernel<<<BATCH * DIM / (256 * 4), 256>>>(out);
}